// round 2
// baseline (speedup 1.0000x reference)
#include <cuda_runtime.h>
#include <math.h>

// Problem constants
#define T_LEN 1200
#define BATCH 32
#define IDIM  512
#define HDIM  512
#define G4    2048            // 4*H
#define XPN   78643200        // T*B*4H
#define NCTA  128             // persistent recurrence grid

// Scratch (device globals — no runtime allocation allowed)
__device__ float g_xp[2][XPN];              // [dir][(t*B+b)*4H + n]
__device__ float g_h[2][2][BATCH * HDIM];   // [parity][dir][b*H+j]
__device__ float g_c[2][BATCH * HDIM];      // [dir][b*H+j]  (final c_n)
__device__ unsigned g_arrive;               // grid-barrier counter

// ---------------------------------------------------------------------------
// Zero / init kernels
// ---------------------------------------------------------------------------
__global__ void zero_out_kernel(float4* __restrict__ o) {
    const int n4 = (T_LEN * BATCH * HDIM) / 4;
    for (int i = blockIdx.x * blockDim.x + threadIdx.x; i < n4;
         i += gridDim.x * blockDim.x)
        o[i] = make_float4(0.f, 0.f, 0.f, 0.f);
}

__global__ void zero_state_kernel() {
    int i = blockIdx.x * blockDim.x + threadIdx.x;  // 32768 threads
    if (i < 2 * BATCH * HDIM)
        (&g_h[0][0][0])[i] = 0.f;   // parity-0 h for both dirs (t=0 reads this)
    if (i == 0) g_arrive = 0u;      // reset grid barrier for this replay
}

// ---------------------------------------------------------------------------
// Input projection GEMM: out[dir][(t*B+b), n] = dot(x_row, W[n,:]) + b1[n]+b2[n]
// M=38400, N=2048, K=512. 128x128 CTA tile, 8x8 per thread, double-buffered.
// rev=1: gathered rows (reversed sequences), matching jnp.take_along_axis.
// ---------------------------------------------------------------------------
__global__ __launch_bounds__(256, 2)
void xproj_gemm(const float* __restrict__ x, const int* __restrict__ lens,
                const float* __restrict__ w, const float* __restrict__ b1,
                const float* __restrict__ b2, int rev)
{
    __shared__ float as[2][8][132];
    __shared__ float bs[2][8][132];
    float* __restrict__ out = g_xp[rev];

    const int tid = threadIdx.x;
    const int m0 = blockIdx.x * 128;
    const int n0 = blockIdx.y * 128;

    const int lr = tid >> 1;          // 0..127
    const int lk = (tid & 1) * 4;     // 0 or 4

    const int m = m0 + lr;
    const float* arow;
    if (!rev) {
        arow = x + (size_t)m * IDIM;
    } else {
        int t = m >> 5, b = m & 31;
        int st = lens[b] - 1 - t;
        if (st < 0) st = 0;
        arow = x + ((size_t)st * BATCH + b) * IDIM;
    }
    const float* brow = w + (size_t)(n0 + lr) * IDIM;

    float4 areg = *(const float4*)(arow + lk);
    float4 breg = *(const float4*)(brow + lk);

    float acc[8][8];
#pragma unroll
    for (int i = 0; i < 8; i++)
#pragma unroll
        for (int j = 0; j < 8; j++) acc[i][j] = 0.f;

    const int wid = tid >> 5, lane = tid & 31;
    const int wm = (wid >> 1) * 32, wn = (wid & 1) * 64;
    const int lm = (lane & 3) * 4,  ln = (lane >> 2) * 4;

    as[0][lk + 0][lr] = areg.x; as[0][lk + 1][lr] = areg.y;
    as[0][lk + 2][lr] = areg.z; as[0][lk + 3][lr] = areg.w;
    bs[0][lk + 0][lr] = breg.x; bs[0][lk + 1][lr] = breg.y;
    bs[0][lk + 2][lr] = breg.z; bs[0][lk + 3][lr] = breg.w;
    __syncthreads();

    int buf = 0;
    for (int k0 = 8; k0 <= IDIM; k0 += 8) {
        const bool more = (k0 < IDIM);
        if (more) {
            areg = *(const float4*)(arow + k0 + lk);
            breg = *(const float4*)(brow + k0 + lk);
        }
#pragma unroll
        for (int kk = 0; kk < 8; kk++) {
            float4 a0  = *(const float4*)&as[buf][kk][wm + lm];
            float4 a1  = *(const float4*)&as[buf][kk][wm + lm + 16];
            float4 b0v = *(const float4*)&bs[buf][kk][wn + ln];
            float4 b1v = *(const float4*)&bs[buf][kk][wn + ln + 32];
            float av[8] = {a0.x, a0.y, a0.z, a0.w, a1.x, a1.y, a1.z, a1.w};
            float bv[8] = {b0v.x, b0v.y, b0v.z, b0v.w, b1v.x, b1v.y, b1v.z, b1v.w};
#pragma unroll
            for (int i = 0; i < 8; i++)
#pragma unroll
                for (int j = 0; j < 8; j++)
                    acc[i][j] += av[i] * bv[j];
        }
        if (more) {
            buf ^= 1;
            as[buf][lk + 0][lr] = areg.x; as[buf][lk + 1][lr] = areg.y;
            as[buf][lk + 2][lr] = areg.z; as[buf][lk + 3][lr] = areg.w;
            bs[buf][lk + 0][lr] = breg.x; bs[buf][lk + 1][lr] = breg.y;
            bs[buf][lk + 2][lr] = breg.z; bs[buf][lk + 3][lr] = breg.w;
            __syncthreads();
        }
    }

    float bias[8];
#pragma unroll
    for (int j = 0; j < 8; j++) {
        int c = n0 + wn + ln + (j & 3) + ((j >= 4) ? 32 : 0);
        bias[j] = b1[c] + b2[c];
    }
#pragma unroll
    for (int i = 0; i < 8; i++) {
        int r = m0 + wm + lm + (i & 3) + ((i >= 4) ? 16 : 0);
        float* orow = out + (size_t)r * G4 + n0 + wn + ln;
#pragma unroll
        for (int j = 0; j < 4; j++) orow[j]      = acc[i][j]     + bias[j];
#pragma unroll
        for (int j = 0; j < 4; j++) orow[32 + j] = acc[i][j + 4] + bias[j + 4];
    }
}

// ---------------------------------------------------------------------------
// Persistent recurrence kernel: ONE launch runs all 1200 timesteps.
// Grid: 128 CTAs = dir(2) x 64 j-blocks of 8. Block: 128 threads. 1 CTA/SM,
// all resident -> software grid barrier is deadlock-free.
// W_hh rows live in SMEM for the whole kernel; h exchanged through L2 (.cg);
// c and the thread's own h live in registers for all 1200 steps.
// ---------------------------------------------------------------------------
#define WSP 516                            // 512 + pad (keeps 16B align)
#define STEP_SMEM (2 * 32 * WSP * 4)       // 132,096 bytes

__global__ __launch_bounds__(128)
void lstm_persist(const float* __restrict__ whh_f,
                  const float* __restrict__ whh_b,
                  const int* __restrict__ lens, float* __restrict__ out)
{
    extern __shared__ float sm[];
    float* ws = sm;                    // [32 rows][WSP]   W_hh slice (persistent)
    float* hs = sm + 32 * WSP;         // [32 b]   [WSP]   h broadcast buffer

    const int dir = blockIdx.x >> 6;
    const int j0  = (blockIdx.x & 63) << 3;
    const float* __restrict__ whh = dir ? whh_b : whh_f;
    const int tid = threadIdx.x;

    // Load W_hh rows once: r = g*8+jj -> global row g*512 + j0 + jj
#pragma unroll
    for (int f = 0; f < 32; f++) {
        int idx = f * 128 + tid;
        int r = idx >> 7, c = (idx & 127) << 2;
        int gg_ = r >> 3, jj_ = r & 7;
        *(float4*)(ws + r * WSP + c) =
            *(const float4*)(whh + (size_t)(gg_ * HDIM + j0 + jj_) * HDIM + c);
    }

    const int jj = tid & 7;
    const int bg = tid >> 3;          // 0..15
    const int b0 = bg, b1 = bg + 16;
    const int j  = j0 + jj;
    const int lenA = lens[b0], lenB = lens[b1];

    float c0 = 0.f, c1 = 0.f, h0 = 0.f, h1 = 0.f;

    const float* w0 = ws + (0 * 8 + jj) * WSP;
    const float* w1 = ws + (1 * 8 + jj) * WSP;
    const float* w2 = ws + (2 * 8 + jj) * WSP;
    const float* w3 = ws + (3 * 8 + jj) * WSP;
    const float* h0p = hs + b0 * WSP;
    const float* h1p = hs + b1 * WSP;

    float* __restrict__ cA = &g_c[dir][b0 * HDIM + j];
    float* __restrict__ cB = &g_c[dir][b1 * HDIM + j];

    __syncthreads();  // ws ready

    for (int t = 0; t < T_LEN; t++) {
        const float* __restrict__ xp = g_xp[dir] + (size_t)t * BATCH * G4;

        // Prefetch x_proj gate values (DRAM stream; overlaps with h load+dot)
        float xa0 = xp[(size_t)b0 * G4 + j];
        float xa1 = xp[(size_t)b0 * G4 + 512 + j];
        float xa2 = xp[(size_t)b0 * G4 + 1024 + j];
        float xa3 = xp[(size_t)b0 * G4 + 1536 + j];
        float xb0 = xp[(size_t)b1 * G4 + j];
        float xb1 = xp[(size_t)b1 * G4 + 512 + j];
        float xb2 = xp[(size_t)b1 * G4 + 1024 + j];
        float xb3 = xp[(size_t)b1 * G4 + 1536 + j];

        // Load h (written by other SMs) into SMEM — must bypass L1 (.cg)
        const float* __restrict__ hin = g_h[t & 1][dir];
#pragma unroll
        for (int f = 0; f < 32; f++) {
            int idx = f * 128 + tid;
            int b = idx >> 7, cc = (idx & 127) << 2;
            float4 v = __ldcg((const float4*)(hin + b * HDIM + cc));
            *(float4*)(hs + b * WSP + cc) = v;
        }
        __syncthreads();

        float acc[4][2];
#pragma unroll
        for (int g = 0; g < 4; g++) { acc[g][0] = 0.f; acc[g][1] = 0.f; }

#pragma unroll 4
        for (int k = 0; k < HDIM; k += 4) {
            float4 hv0 = *(const float4*)(h0p + k);
            float4 hv1 = *(const float4*)(h1p + k);
            float4 wv;
            wv = *(const float4*)(w0 + k);
            acc[0][0] += wv.x * hv0.x + wv.y * hv0.y + wv.z * hv0.z + wv.w * hv0.w;
            acc[0][1] += wv.x * hv1.x + wv.y * hv1.y + wv.z * hv1.z + wv.w * hv1.w;
            wv = *(const float4*)(w1 + k);
            acc[1][0] += wv.x * hv0.x + wv.y * hv0.y + wv.z * hv0.z + wv.w * hv0.w;
            acc[1][1] += wv.x * hv1.x + wv.y * hv1.y + wv.z * hv1.z + wv.w * hv1.w;
            wv = *(const float4*)(w2 + k);
            acc[2][0] += wv.x * hv0.x + wv.y * hv0.y + wv.z * hv0.z + wv.w * hv0.w;
            acc[2][1] += wv.x * hv1.x + wv.y * hv1.y + wv.z * hv1.z + wv.w * hv1.w;
            wv = *(const float4*)(w3 + k);
            acc[3][0] += wv.x * hv0.x + wv.y * hv0.y + wv.z * hv0.z + wv.w * hv0.w;
            acc[3][1] += wv.x * hv1.x + wv.y * hv1.y + wv.z * hv1.z + wv.w * hv1.w;
        }

        float* __restrict__ hout = g_h[(t + 1) & 1][dir];

        // ---- cell update, batch b0 ----
        {
            float gi = acc[0][0] + xa0;
            float gf = acc[1][0] + xa1;
            float gg = acc[2][0] + xa2;
            float go = acc[3][0] + xa3;
            if (t < lenA) {
                gi = 1.f / (1.f + __expf(-gi));
                gf = 1.f / (1.f + __expf(-gf));
                gg = tanhf(gg);
                go = 1.f / (1.f + __expf(-go));
                c0 = gf * c0 + gi * gg;
                h0 = go * tanhf(c0);
                *cA = c0;
                const int to = dir ? (lenA - 1 - t) : t;
                atomicAdd(out + ((size_t)to * BATCH + b0) * HDIM + j, h0);
            }
            hout[b0 * HDIM + j] = h0;  // frozen past length
        }
        // ---- cell update, batch b1 ----
        {
            float gi = acc[0][1] + xb0;
            float gf = acc[1][1] + xb1;
            float gg = acc[2][1] + xb2;
            float go = acc[3][1] + xb3;
            if (t < lenB) {
                gi = 1.f / (1.f + __expf(-gi));
                gf = 1.f / (1.f + __expf(-gf));
                gg = tanhf(gg);
                go = 1.f / (1.f + __expf(-go));
                c1 = gf * c1 + gi * gg;
                h1 = go * tanhf(c1);
                *cB = c1;
                const int to = dir ? (lenB - 1 - t) : t;
                atomicAdd(out + ((size_t)to * BATCH + b1) * HDIM + j, h1);
            }
            hout[b1 * HDIM + j] = h1;
        }

        // ---- grid barrier (all 128 CTAs resident -> safe) ----
        __threadfence();      // publish this thread's h stores to L2
        __syncthreads();      // all threads' fences done; hs reads finished
        if (tid == 0) {
            atomicAdd(&g_arrive, 1u);
            const unsigned target = (unsigned)(t + 1) * NCTA;
            while (*(volatile unsigned*)&g_arrive < target) { }
            __threadfence();  // acquire
        }
        __syncthreads();
    }
}

// ---------------------------------------------------------------------------
// Copy final states h_n (2,B,H) and c_n (2,B,H) to output tail.
// After 1200 steps the live h buffer is parity 0.
// ---------------------------------------------------------------------------
__global__ void finalize_kernel(float* __restrict__ out) {
    int i = blockIdx.x * blockDim.x + threadIdx.x;  // 0..32767
    if (i < 2 * BATCH * HDIM) {
        const size_t base = (size_t)T_LEN * BATCH * HDIM;
        int d = i >> 14, r = i & 16383;
        out[base + i] = g_h[0][d][r];
        out[base + 2 * BATCH * HDIM + i] = g_c[d][r];
    }
}

// ---------------------------------------------------------------------------
extern "C" void kernel_launch(void* const* d_in, const int* in_sizes, int n_in,
                              void* d_out, int out_size) {
    (void)in_sizes; (void)n_in; (void)out_size;
    const float* x      = (const float*)d_in[0];
    const int*   lens   = (const int*)d_in[1];
    const float* w_ih_f = (const float*)d_in[2];
    const float* w_hh_f = (const float*)d_in[3];
    const float* b_ih_f = (const float*)d_in[4];
    const float* b_hh_f = (const float*)d_in[5];
    const float* w_ih_b = (const float*)d_in[6];
    const float* w_hh_b = (const float*)d_in[7];
    const float* b_ih_b = (const float*)d_in[8];
    const float* b_hh_b = (const float*)d_in[9];
    float* out = (float*)d_out;

    cudaFuncSetAttribute(lstm_persist,
                         cudaFuncAttributeMaxDynamicSharedMemorySize, STEP_SMEM);

    zero_out_kernel<<<2048, 256>>>((float4*)out);
    zero_state_kernel<<<128, 256>>>();

    dim3 gg(300, 16);  // M/128 x N/128
    xproj_gemm<<<gg, 256>>>(x, lens, w_ih_f, b_ih_f, b_hh_f, 0);
    xproj_gemm<<<gg, 256>>>(x, lens, w_ih_b, b_ih_b, b_hh_b, 1);

    lstm_persist<<<NCTA, 128, STEP_SMEM>>>(w_hh_f, w_hh_b, lens, out);

    finalize_kernel<<<128, 256>>>(out);
}

// round 3
// speedup vs baseline: 1.0786x; 1.0786x over previous
#include <cuda_runtime.h>
#include <math.h>

// Problem constants
#define T_LEN 1200
#define BATCH 32
#define IDIM  512
#define HDIM  512
#define G4    2048            // 4*H
#define XPN   78643200        // T*B*4H
#define NCTA  128             // persistent recurrence grid
#define NTHR  256

// Scratch (device globals — no runtime allocation allowed)
__device__ float g_xp[2][XPN];              // [dir][(t*B+b)*4H + n]
__device__ float g_h[2][BATCH * HDIM];      // [dir][b*H+j]   (single buffer)
__device__ float g_part[NCTA * 8192];       // split-K partial gate sums
__device__ unsigned g_arrive;               // grid-barrier counter

// ---------------------------------------------------------------------------
// Zero / init kernels
// ---------------------------------------------------------------------------
__global__ void zero_out_kernel(float4* __restrict__ o) {
    const int n4 = (T_LEN * BATCH * HDIM) / 4;
    for (int i = blockIdx.x * blockDim.x + threadIdx.x; i < n4;
         i += gridDim.x * blockDim.x)
        o[i] = make_float4(0.f, 0.f, 0.f, 0.f);
}

__global__ void zero_state_kernel() {
    int i = blockIdx.x * blockDim.x + threadIdx.x;  // 32768 threads
    if (i < 2 * BATCH * HDIM)
        (&g_h[0][0])[i] = 0.f;      // h = 0 for both dirs
    if (i == 0) g_arrive = 0u;      // reset grid barrier for this replay
}

// ---------------------------------------------------------------------------
// Input projection GEMM (unchanged): M=38400, N=2048, K=512.
// ---------------------------------------------------------------------------
__global__ __launch_bounds__(256, 2)
void xproj_gemm(const float* __restrict__ x, const int* __restrict__ lens,
                const float* __restrict__ w, const float* __restrict__ b1,
                const float* __restrict__ b2, int rev)
{
    __shared__ float as[2][8][132];
    __shared__ float bs[2][8][132];
    float* __restrict__ out = g_xp[rev];

    const int tid = threadIdx.x;
    const int m0 = blockIdx.x * 128;
    const int n0 = blockIdx.y * 128;

    const int lr = tid >> 1;
    const int lk = (tid & 1) * 4;

    const int m = m0 + lr;
    const float* arow;
    if (!rev) {
        arow = x + (size_t)m * IDIM;
    } else {
        int t = m >> 5, b = m & 31;
        int st = lens[b] - 1 - t;
        if (st < 0) st = 0;
        arow = x + ((size_t)st * BATCH + b) * IDIM;
    }
    const float* brow = w + (size_t)(n0 + lr) * IDIM;

    float4 areg = *(const float4*)(arow + lk);
    float4 breg = *(const float4*)(brow + lk);

    float acc[8][8];
#pragma unroll
    for (int i = 0; i < 8; i++)
#pragma unroll
        for (int j = 0; j < 8; j++) acc[i][j] = 0.f;

    const int wid = tid >> 5, lane = tid & 31;
    const int wm = (wid >> 1) * 32, wn = (wid & 1) * 64;
    const int lm = (lane & 3) * 4,  ln = (lane >> 2) * 4;

    as[0][lk + 0][lr] = areg.x; as[0][lk + 1][lr] = areg.y;
    as[0][lk + 2][lr] = areg.z; as[0][lk + 3][lr] = areg.w;
    bs[0][lk + 0][lr] = breg.x; bs[0][lk + 1][lr] = breg.y;
    bs[0][lk + 2][lr] = breg.z; bs[0][lk + 3][lr] = breg.w;
    __syncthreads();

    int buf = 0;
    for (int k0 = 8; k0 <= IDIM; k0 += 8) {
        const bool more = (k0 < IDIM);
        if (more) {
            areg = *(const float4*)(arow + k0 + lk);
            breg = *(const float4*)(brow + k0 + lk);
        }
#pragma unroll
        for (int kk = 0; kk < 8; kk++) {
            float4 a0  = *(const float4*)&as[buf][kk][wm + lm];
            float4 a1  = *(const float4*)&as[buf][kk][wm + lm + 16];
            float4 b0v = *(const float4*)&bs[buf][kk][wn + ln];
            float4 b1v = *(const float4*)&bs[buf][kk][wn + ln + 32];
            float av[8] = {a0.x, a0.y, a0.z, a0.w, a1.x, a1.y, a1.z, a1.w};
            float bv[8] = {b0v.x, b0v.y, b0v.z, b0v.w, b1v.x, b1v.y, b1v.z, b1v.w};
#pragma unroll
            for (int i = 0; i < 8; i++)
#pragma unroll
                for (int j = 0; j < 8; j++)
                    acc[i][j] += av[i] * bv[j];
        }
        if (more) {
            buf ^= 1;
            as[buf][lk + 0][lr] = areg.x; as[buf][lk + 1][lr] = areg.y;
            as[buf][lk + 2][lr] = areg.z; as[buf][lk + 3][lr] = areg.w;
            bs[buf][lk + 0][lr] = breg.x; bs[buf][lk + 1][lr] = breg.y;
            bs[buf][lk + 2][lr] = breg.z; bs[buf][lk + 3][lr] = breg.w;
            __syncthreads();
        }
    }

    float bias[8];
#pragma unroll
    for (int j = 0; j < 8; j++) {
        int c = n0 + wn + ln + (j & 3) + ((j >= 4) ? 32 : 0);
        bias[j] = b1[c] + b2[c];
    }
#pragma unroll
    for (int i = 0; i < 8; i++) {
        int r = m0 + wm + lm + (i & 3) + ((i >= 4) ? 16 : 0);
        float* orow = out + (size_t)r * G4 + n0 + wn + ln;
#pragma unroll
        for (int j = 0; j < 4; j++) orow[j]      = acc[i][j]     + bias[j];
#pragma unroll
        for (int j = 0; j < 4; j++) orow[32 + j] = acc[i][j + 4] + bias[j + 4];
    }
}

// ---------------------------------------------------------------------------
// Persistent recurrence: 128 CTAs = 2 dir x 8 jb x 8 ksplit, 256 threads.
// Phase 1 (all CTAs): partial gate GEMM over k-chunk -> g_part.
// Phase 2 (all CTAs): reduce 8 partials, LSTM cell (c,h in registers).
// Two grid barriers per step. W_hh slice persistent in SMEM.
// ---------------------------------------------------------------------------
#define WPAD 68                                   // row stride (floats)
#define SMEM_BYTES (120 * 1024)                   // force 1 CTA/SM

__global__ __launch_bounds__(NTHR)
void lstm_persist(const float* __restrict__ whh_f,
                  const float* __restrict__ whh_b,
                  const int* __restrict__ lens, float* __restrict__ out)
{
    extern __shared__ float sm[];
    float* ws = sm;                 // [256 rows][WPAD]  W_hh slice (persistent)
    float* hs = sm + 256 * WPAD;    // [32 b]   [WPAD]  h k-chunk

    const int bid = blockIdx.x;
    const int dir = bid >> 6;
    const int r   = bid & 63;
    const int jb  = r >> 3;         // 0..7  (64 j each)
    const int ks  = r & 7;          // 0..7  (64 k each)
    const int j0  = jb << 6;
    const int k0  = ks << 6;
    const int tid = threadIdx.x;

    const float* __restrict__ whh = dir ? whh_b : whh_f;

    // Load W_hh slice once: storage row a (0..255) <-> gate row g*512+j0+jl,
    // cols k0..k0+63.  (g = a>>6, jl = a&63)
#pragma unroll
    for (int it = 0; it < 16; it++) {
        int idx = it * 256 + tid;          // 0..4095 float4s
        int a  = idx >> 4;
        int kk = (idx & 15) << 2;
        int g  = a >> 6, jl = a & 63;
        *(float4*)(ws + a * WPAD + kk) =
            *(const float4*)(whh + (size_t)(g * HDIM + j0 + jl) * HDIM + k0 + kk);
    }

    // Phase-1 identity: rg = rows, bg = batch group
    const int rg = tid >> 3;        // 0..31 ; rows a = rg + 32*i
    const int bg = tid & 7;         // 0..7  ; batches b = bg*4 .. +3

    // Phase-2 identity: one cell per thread
    const int jl_c = (ks << 3) + (tid & 7);   // CTA reduces jl slice [ks*8, +8)
    const int b_c  = tid >> 3;                // 0..31
    const int j_c  = j0 + jl_c;
    const int len_c = lens[b_c];

    float c_reg = 0.f, h_reg = 0.f;

    float* __restrict__ hbuf = g_h[dir];
    float* __restrict__ pbase = g_part + (size_t)bid * 8192;
    const size_t pgrp = (size_t)(dir * 64 + jb * 8) * 8192;  // group base

    __syncthreads();  // ws ready

    for (int t = 0; t < T_LEN; t++) {
        // Prefetch xp for this thread's phase-2 cell (consumed after barrier1)
        const float* xpr = g_xp[dir] + ((size_t)t * BATCH + b_c) * G4 + j_c;
        float xg0 = xpr[0];
        float xg1 = xpr[512];
        float xg2 = xpr[1024];
        float xg3 = xpr[1536];

        // Load h k-chunk into SMEM (L2-coherent loads)
#pragma unroll
        for (int it = 0; it < 2; it++) {
            int idx = it * 256 + tid;      // 0..511 float4s
            int b  = idx >> 4;
            int kk = (idx & 15) << 2;
            float4 v = __ldcg((const float4*)(hbuf + b * HDIM + k0 + kk));
            *(float4*)(hs + b * WPAD + kk) = v;
        }
        __syncthreads();

        // ---- Phase 1: partial GEMM, rows a = rg+32i, batches bg*4+bb ----
        float acc[8][4];
#pragma unroll
        for (int i = 0; i < 8; i++)
#pragma unroll
            for (int bb = 0; bb < 4; bb++) acc[i][bb] = 0.f;

#pragma unroll 4
        for (int k4 = 0; k4 < 16; k4++) {
            const int k = k4 << 2;
            float4 hv[4];
#pragma unroll
            for (int bb = 0; bb < 4; bb++)
                hv[bb] = *(const float4*)(hs + (bg * 4 + bb) * WPAD + k);
#pragma unroll
            for (int i = 0; i < 8; i++) {
                float4 wv = *(const float4*)(ws + (rg + 32 * i) * WPAD + k);
#pragma unroll
                for (int bb = 0; bb < 4; bb++)
                    acc[i][bb] += wv.x * hv[bb].x + wv.y * hv[bb].y +
                                  wv.z * hv[bb].z + wv.w * hv[bb].w;
            }
        }

        // Store partials: layout [g][jl][b] within this CTA's 8192 chunk
#pragma unroll
        for (int i = 0; i < 8; i++) {
            int g  = i >> 1;
            int jl = rg + ((i & 1) << 5);
            *(float4*)(pbase + ((g << 6) + jl) * 32 + (bg << 2)) =
                make_float4(acc[i][0], acc[i][1], acc[i][2], acc[i][3]);
        }

        // ---- barrier 1 ----
        __threadfence();
        __syncthreads();
        if (tid == 0) {
            atomicAdd(&g_arrive, 1u);
            const unsigned tgt = (unsigned)(2 * t + 1) * NCTA;
            while (*(volatile unsigned*)&g_arrive < tgt) { }
            __threadfence();
        }
        __syncthreads();

        // ---- Phase 2: reduce 8 k-split partials, run cell ----
        float s0 = xg0, s1 = xg1, s2 = xg2, s3 = xg3;
#pragma unroll
        for (int q = 0; q < 8; q++) {
            const float* pq = g_part + pgrp + (size_t)q * 8192 + jl_c * 32 + b_c;
            s0 += __ldcg(pq + 0 * 2048);
            s1 += __ldcg(pq + 1 * 2048);
            s2 += __ldcg(pq + 2 * 2048);
            s3 += __ldcg(pq + 3 * 2048);
        }

        if (t < len_c) {
            float gi = 1.f / (1.f + __expf(-s0));
            float gf = 1.f / (1.f + __expf(-s1));
            float gg = tanhf(s2);
            float go = 1.f / (1.f + __expf(-s3));
            c_reg = gf * c_reg + gi * gg;
            h_reg = go * tanhf(c_reg);
            __stcg(hbuf + b_c * HDIM + j_c, h_reg);
            const int to = dir ? (len_c - 1 - t) : t;
            atomicAdd(out + ((size_t)to * BATCH + b_c) * HDIM + j_c, h_reg);
        }
        // frozen b: h stays in global unchanged (single buffer)

        // ---- barrier 2 ----
        __threadfence();
        __syncthreads();
        if (tid == 0) {
            atomicAdd(&g_arrive, 1u);
            const unsigned tgt = (unsigned)(2 * t + 2) * NCTA;
            while (*(volatile unsigned*)&g_arrive < tgt) { }
            __threadfence();
        }
        __syncthreads();
    }

    // Final states from registers: h_n (2,B,H) then c_n (2,B,H)
    const size_t base = (size_t)T_LEN * BATCH * HDIM;
    out[base + dir * BATCH * HDIM + b_c * HDIM + j_c] = h_reg;
    out[base + 2 * BATCH * HDIM + dir * BATCH * HDIM + b_c * HDIM + j_c] = c_reg;
}

// ---------------------------------------------------------------------------
extern "C" void kernel_launch(void* const* d_in, const int* in_sizes, int n_in,
                              void* d_out, int out_size) {
    (void)in_sizes; (void)n_in; (void)out_size;
    const float* x      = (const float*)d_in[0];
    const int*   lens   = (const int*)d_in[1];
    const float* w_ih_f = (const float*)d_in[2];
    const float* w_hh_f = (const float*)d_in[3];
    const float* b_ih_f = (const float*)d_in[4];
    const float* b_hh_f = (const float*)d_in[5];
    const float* w_ih_b = (const float*)d_in[6];
    const float* w_hh_b = (const float*)d_in[7];
    const float* b_ih_b = (const float*)d_in[8];
    const float* b_hh_b = (const float*)d_in[9];
    float* out = (float*)d_out;

    cudaFuncSetAttribute(lstm_persist,
                         cudaFuncAttributeMaxDynamicSharedMemorySize, SMEM_BYTES);

    zero_out_kernel<<<2048, 256>>>((float4*)out);
    zero_state_kernel<<<128, 256>>>();

    dim3 gg(300, 16);  // M/128 x N/128
    xproj_gemm<<<gg, 256>>>(x, lens, w_ih_f, b_ih_f, b_hh_f, 0);
    xproj_gemm<<<gg, 256>>>(x, lens, w_ih_b, b_ih_b, b_hh_b, 1);

    lstm_persist<<<NCTA, NTHR, SMEM_BYTES>>>(w_hh_f, w_hh_b, lens, out);
}

// round 4
// speedup vs baseline: 1.1358x; 1.0530x over previous
#include <cuda_runtime.h>
#include <math.h>

// Problem constants
#define T_LEN 1200
#define BATCH 32
#define IDIM  512
#define HDIM  512
#define G4    2048            // 4*H
#define XPN   78643200        // T*B*4H
#define NCTA  128             // persistent recurrence grid
#define NTHR  256

typedef unsigned long long u64;

// Packed fp32x2 FMA (sm_103a FFMA2 — only reachable via PTX)
__device__ __forceinline__ void fma2(u64& d, u64 a, u64 b) {
    asm("fma.rn.f32x2 %0, %1, %2, %0;" : "+l"(d) : "l"(a), "l"(b));
}
__device__ __forceinline__ float2 unp2(u64 v) {
    float2 r; asm("mov.b64 {%0, %1}, %2;" : "=f"(r.x), "=f"(r.y) : "l"(v));
    return r;
}
__device__ __forceinline__ u64 dup2(float v) {
    u64 r; asm("mov.b64 %0, {%1, %1};" : "=l"(r) : "f"(v));
    return r;
}

// Scratch (device globals — no runtime allocation allowed)
// x_proj layout: [dir][ (t*2048 + g*512 + j) * 32 + b ]   (batch-minor!)
__device__ float g_xp[2][XPN];
__device__ float g_h[2][BATCH * HDIM];      // [dir][b*H+j]  (single buffer)
__device__ float g_part[NCTA * 8192];       // split-K partials [cta][(g*64+jl)*32+b]
__device__ unsigned g_arrive;               // grid-barrier counter

// ---------------------------------------------------------------------------
// Zero / init kernels
// ---------------------------------------------------------------------------
__global__ void zero_out_kernel(float4* __restrict__ o) {
    const int n4 = (T_LEN * BATCH * HDIM) / 4;
    for (int i = blockIdx.x * blockDim.x + threadIdx.x; i < n4;
         i += gridDim.x * blockDim.x)
        o[i] = make_float4(0.f, 0.f, 0.f, 0.f);
}

__global__ void zero_state_kernel() {
    int i = blockIdx.x * blockDim.x + threadIdx.x;  // 32768 threads
    if (i < 2 * BATCH * HDIM)
        (&g_h[0][0])[i] = 0.f;
    if (i == 0) g_arrive = 0u;
}

// ---------------------------------------------------------------------------
// Input projection GEMM with packed f32x2 FMA.
// M=38400 (t,b), N=2048, K=512. 128x128 tile, 8m x (4 n-pairs) per thread.
// Output written in [t][n][b] layout (batch-minor) for recurrence coalescing.
// ---------------------------------------------------------------------------
__global__ __launch_bounds__(256, 2)
void xproj_gemm(const float* __restrict__ x, const int* __restrict__ lens,
                const float* __restrict__ w, const float* __restrict__ b1,
                const float* __restrict__ b2, int rev)
{
    __shared__ float as[2][8][132];
    __shared__ float bs[2][8][132];
    float* __restrict__ out = g_xp[rev];

    const int tid = threadIdx.x;
    const int m0 = blockIdx.x * 128;
    const int n0 = blockIdx.y * 128;

    const int lr = tid >> 1;
    const int lk = (tid & 1) * 4;

    const int m = m0 + lr;
    const float* arow;
    if (!rev) {
        arow = x + (size_t)m * IDIM;
    } else {
        int t = m >> 5, b = m & 31;
        int st = lens[b] - 1 - t;
        if (st < 0) st = 0;
        arow = x + ((size_t)st * BATCH + b) * IDIM;
    }
    const float* brow = w + (size_t)(n0 + lr) * IDIM;

    float4 areg = *(const float4*)(arow + lk);
    float4 breg = *(const float4*)(brow + lk);

    u64 acc2[8][4];
#pragma unroll
    for (int i = 0; i < 8; i++)
#pragma unroll
        for (int p = 0; p < 4; p++) acc2[i][p] = 0ULL;

    const int wid = tid >> 5, lane = tid & 31;
    const int wm = (wid >> 1) * 32, wn = (wid & 1) * 64;
    const int lm = (lane & 3) * 4,  ln = (lane >> 2) * 4;

    as[0][lk + 0][lr] = areg.x; as[0][lk + 1][lr] = areg.y;
    as[0][lk + 2][lr] = areg.z; as[0][lk + 3][lr] = areg.w;
    bs[0][lk + 0][lr] = breg.x; bs[0][lk + 1][lr] = breg.y;
    bs[0][lk + 2][lr] = breg.z; bs[0][lk + 3][lr] = breg.w;
    __syncthreads();

    int buf = 0;
    for (int k0 = 8; k0 <= IDIM; k0 += 8) {
        const bool more = (k0 < IDIM);
        if (more) {
            areg = *(const float4*)(arow + k0 + lk);
            breg = *(const float4*)(brow + k0 + lk);
        }
#pragma unroll
        for (int kk = 0; kk < 8; kk++) {
            float4 a0  = *(const float4*)&as[buf][kk][wm + lm];
            float4 a1  = *(const float4*)&as[buf][kk][wm + lm + 16];
            ulonglong2 bq0 = *(const ulonglong2*)&bs[buf][kk][wn + ln];
            ulonglong2 bq1 = *(const ulonglong2*)&bs[buf][kk][wn + ln + 32];
            u64 b2v[4] = {bq0.x, bq0.y, bq1.x, bq1.y};
            float av[8] = {a0.x, a0.y, a0.z, a0.w, a1.x, a1.y, a1.z, a1.w};
#pragma unroll
            for (int i = 0; i < 8; i++) {
                u64 a2 = dup2(av[i]);
#pragma unroll
                for (int p = 0; p < 4; p++)
                    fma2(acc2[i][p], a2, b2v[p]);
            }
        }
        if (more) {
            buf ^= 1;
            as[buf][lk + 0][lr] = areg.x; as[buf][lk + 1][lr] = areg.y;
            as[buf][lk + 2][lr] = areg.z; as[buf][lk + 3][lr] = areg.w;
            bs[buf][lk + 0][lr] = breg.x; bs[buf][lk + 1][lr] = breg.y;
            bs[buf][lk + 2][lr] = breg.z; bs[buf][lk + 3][lr] = breg.w;
            __syncthreads();
        }
    }

    // Epilogue: n-pair p covers columns c0 + {0,1}, {2,3}, {32,33}, {34,35}
    const int c0 = n0 + wn + ln;
    float bias[8];
#pragma unroll
    for (int p = 0; p < 4; p++) {
        int cc = c0 + (p & 1) * 2 + (p >> 1) * 32;
        bias[p * 2 + 0] = b1[cc + 0] + b2[cc + 0];
        bias[p * 2 + 1] = b1[cc + 1] + b2[cc + 1];
    }
#pragma unroll
    for (int i = 0; i < 8; i++) {
        int r = m0 + wm + lm + (i & 3) + ((i >= 4) ? 16 : 0);
        int t_ = r >> 5, b_ = r & 31;
        size_t base = ((size_t)t_ * G4) * 32 + b_;
#pragma unroll
        for (int p = 0; p < 4; p++) {
            int cc = c0 + (p & 1) * 2 + (p >> 1) * 32;
            float2 v = unp2(acc2[i][p]);
            out[base + (size_t)(cc + 0) * 32] = v.x + bias[p * 2 + 0];
            out[base + (size_t)(cc + 1) * 32] = v.y + bias[p * 2 + 1];
        }
    }
}

// ---------------------------------------------------------------------------
// Persistent recurrence: 128 CTAs = 2 dir x 8 jb x 8 ksplit, 256 threads.
// Phase 1: partial gate GEMM over k-chunk with f32x2 FMA -> g_part.
// Phase 2: reduce 8 partials (coalesced), LSTM cell (c,h in registers).
// Two grid barriers per step. W_hh slice persistent in SMEM.
// ---------------------------------------------------------------------------
#define WPAD 68
#define SMEM_BYTES (120 * 1024)                   // force 1 CTA/SM

__global__ __launch_bounds__(NTHR)
void lstm_persist(const float* __restrict__ whh_f,
                  const float* __restrict__ whh_b,
                  const int* __restrict__ lens, float* __restrict__ out)
{
    extern __shared__ float sm[];
    float* ws = sm;                 // [256 rows][WPAD]  W_hh slice (persistent)
    float* hs = sm + 256 * WPAD;    // [32 b]   [WPAD]  h k-chunk

    const int bid = blockIdx.x;
    const int dir = bid >> 6;
    const int r   = bid & 63;
    const int jb  = r >> 3;         // 0..7  (64 j each)
    const int ks  = r & 7;          // 0..7  (64 k each)
    const int j0  = jb << 6;
    const int k0  = ks << 6;
    const int tid = threadIdx.x;

    const float* __restrict__ whh = dir ? whh_b : whh_f;

    // Load W_hh slice once: row a (0..255) <-> gate row g*512+j0+jl, cols k0..+63
#pragma unroll
    for (int it = 0; it < 16; it++) {
        int idx = it * 256 + tid;
        int a  = idx >> 4;
        int kk = (idx & 15) << 2;
        int g  = a >> 6, jl = a & 63;
        *(float4*)(ws + a * WPAD + kk) =
            *(const float4*)(whh + (size_t)(g * HDIM + j0 + jl) * HDIM + k0 + kk);
    }

    // Phase-1 identity
    const int rg = tid >> 3;        // 0..31 ; rows a = rg + 32*i
    const int bg = tid & 7;         // 0..7  ; batches b = bg*4 .. +3

    // Phase-2 identity (batch-minor for coalescing)
    const int b_c  = tid & 31;
    const int jl_c = (ks << 3) + (tid >> 5);
    const int j_c  = j0 + jl_c;
    const int len_c = lens[b_c];

    float c_reg = 0.f, h_reg = 0.f;

    float* __restrict__ hbuf = g_h[dir];
    float* __restrict__ pbase = g_part + (size_t)bid * 8192;

    const float* wr[8];
#pragma unroll
    for (int i = 0; i < 8; i++) wr[i] = ws + (rg + 32 * i) * WPAD;
    const float* hp[4];
#pragma unroll
    for (int bb = 0; bb < 4; bb++) hp[bb] = hs + (bg * 4 + bb) * WPAD;

    __syncthreads();  // ws ready

    for (int t = 0; t < T_LEN; t++) {
        // Prefetch xp for this thread's phase-2 cell (coalesced: b-minor)
        const float* xb = g_xp[dir] + ((size_t)t * G4 + j_c) * 32 + b_c;
        float xg0 = xb[0];
        float xg1 = xb[512 * 32];
        float xg2 = xb[1024 * 32];
        float xg3 = xb[1536 * 32];

        // Load h k-chunk into SMEM (L2-coherent loads)
#pragma unroll
        for (int it = 0; it < 2; it++) {
            int idx = it * 256 + tid;
            int b  = idx >> 4;
            int kk = (idx & 15) << 2;
            float4 v = __ldcg((const float4*)(hbuf + b * HDIM + k0 + kk));
            *(float4*)(hs + b * WPAD + kk) = v;
        }
        __syncthreads();

        // ---- Phase 1: partial GEMM, f32x2 pairs over k ----
        u64 acc2[8][4];
#pragma unroll
        for (int i = 0; i < 8; i++)
#pragma unroll
            for (int bb = 0; bb < 4; bb++) acc2[i][bb] = 0ULL;

#pragma unroll 4
        for (int k = 0; k < 64; k += 4) {
            ulonglong2 hq[4];
#pragma unroll
            for (int bb = 0; bb < 4; bb++)
                hq[bb] = *(const ulonglong2*)(hp[bb] + k);
#pragma unroll
            for (int i = 0; i < 8; i++) {
                ulonglong2 wq = *(const ulonglong2*)(wr[i] + k);
#pragma unroll
                for (int bb = 0; bb < 4; bb++) {
                    fma2(acc2[i][bb], wq.x, hq[bb].x);
                    fma2(acc2[i][bb], wq.y, hq[bb].y);
                }
            }
        }

        // Store partials [ (g*64+jl)*32 + b ]
#pragma unroll
        for (int i = 0; i < 8; i++) {
            int g  = i >> 1;
            int jl = rg + ((i & 1) << 5);
            float2 v0 = unp2(acc2[i][0]);
            float2 v1 = unp2(acc2[i][1]);
            float2 v2 = unp2(acc2[i][2]);
            float2 v3 = unp2(acc2[i][3]);
            *(float4*)(pbase + ((g << 6) + jl) * 32 + (bg << 2)) =
                make_float4(v0.x + v0.y, v1.x + v1.y, v2.x + v2.y, v3.x + v3.y);
        }

        // ---- barrier 1 ----
        __threadfence();
        __syncthreads();
        if (tid == 0) {
            atomicAdd(&g_arrive, 1u);
            const unsigned tgt = (unsigned)(2 * t + 1) * NCTA;
            while (*(volatile unsigned*)&g_arrive < tgt) { }
            __threadfence();
        }
        __syncthreads();

        // ---- Phase 2: reduce 8 k-split partials (coalesced), run cell ----
        float s0 = xg0, s1 = xg1, s2 = xg2, s3 = xg3;
        const size_t poff = (size_t)jl_c * 32 + b_c;
#pragma unroll
        for (int q = 0; q < 8; q++) {
            const float* pq =
                g_part + (size_t)(dir * 64 + jb * 8 + q) * 8192 + poff;
            s0 += __ldcg(pq + 0 * 2048);
            s1 += __ldcg(pq + 1 * 2048);
            s2 += __ldcg(pq + 2 * 2048);
            s3 += __ldcg(pq + 3 * 2048);
        }

        if (t < len_c) {
            float gi = 1.f / (1.f + __expf(-s0));
            float gf = 1.f / (1.f + __expf(-s1));
            float gg = tanhf(s2);
            float go = 1.f / (1.f + __expf(-s3));
            c_reg = gf * c_reg + gi * gg;
            h_reg = go * tanhf(c_reg);
            __stcg(hbuf + b_c * HDIM + j_c, h_reg);
            const int to = dir ? (len_c - 1 - t) : t;
            atomicAdd(out + ((size_t)to * BATCH + b_c) * HDIM + j_c, h_reg);
        }

        // ---- barrier 2 ----
        __threadfence();
        __syncthreads();
        if (tid == 0) {
            atomicAdd(&g_arrive, 1u);
            const unsigned tgt = (unsigned)(2 * t + 2) * NCTA;
            while (*(volatile unsigned*)&g_arrive < tgt) { }
            __threadfence();
        }
        __syncthreads();
    }

    // Final states from registers: h_n (2,B,H) then c_n (2,B,H)
    const size_t base = (size_t)T_LEN * BATCH * HDIM;
    out[base + dir * BATCH * HDIM + b_c * HDIM + j_c] = h_reg;
    out[base + 2 * BATCH * HDIM + dir * BATCH * HDIM + b_c * HDIM + j_c] = c_reg;
}

// ---------------------------------------------------------------------------
extern "C" void kernel_launch(void* const* d_in, const int* in_sizes, int n_in,
                              void* d_out, int out_size) {
    (void)in_sizes; (void)n_in; (void)out_size;
    const float* x      = (const float*)d_in[0];
    const int*   lens   = (const int*)d_in[1];
    const float* w_ih_f = (const float*)d_in[2];
    const float* w_hh_f = (const float*)d_in[3];
    const float* b_ih_f = (const float*)d_in[4];
    const float* b_hh_f = (const float*)d_in[5];
    const float* w_ih_b = (const float*)d_in[6];
    const float* w_hh_b = (const float*)d_in[7];
    const float* b_ih_b = (const float*)d_in[8];
    const float* b_hh_b = (const float*)d_in[9];
    float* out = (float*)d_out;

    cudaFuncSetAttribute(lstm_persist,
                         cudaFuncAttributeMaxDynamicSharedMemorySize, SMEM_BYTES);

    zero_out_kernel<<<2048, 256>>>((float4*)out);
    zero_state_kernel<<<128, 256>>>();

    dim3 gg(300, 16);  // M/128 x N/128
    xproj_gemm<<<gg, 256>>>(x, lens, w_ih_f, b_ih_f, b_hh_f, 0);
    xproj_gemm<<<gg, 256>>>(x, lens, w_ih_b, b_ih_b, b_hh_b, 1);

    lstm_persist<<<NCTA, NTHR, SMEM_BYTES>>>(w_hh_f, w_hh_b, lens, out);
}

// round 5
// speedup vs baseline: 1.4762x; 1.2996x over previous
#include <cuda_runtime.h>
#include <math.h>

// Problem constants
#define T_LEN 1200
#define BATCH 32
#define IDIM  512
#define HDIM  512
#define G4    2048            // 4*H
#define XPN   78643200        // T*B*4H
#define NCTA  128             // persistent recurrence grid
#define NTHR  256

typedef unsigned long long u64;

// Packed fp32x2 FMA (throughput-neutral on sm_103a, kept in GEMM — harmless)
__device__ __forceinline__ void fma2(u64& d, u64 a, u64 b) {
    asm("fma.rn.f32x2 %0, %1, %2, %0;" : "+l"(d) : "l"(a), "l"(b));
}
__device__ __forceinline__ float2 unp2(u64 v) {
    float2 r; asm("mov.b64 {%0, %1}, %2;" : "=f"(r.x), "=f"(r.y) : "l"(v));
    return r;
}
__device__ __forceinline__ u64 dup2(float v) {
    u64 r; asm("mov.b64 %0, {%1, %1};" : "=l"(r) : "f"(v));
    return r;
}

// Scratch (device globals — no runtime allocation allowed)
// x_proj layout: [dir][ (t*2048 + g*512 + j) * 32 + b ]   (batch-minor)
__device__ float g_xp[2][XPN];
__device__ float g_h[2][2][BATCH * HDIM];   // [parity][dir][b*512 + j]
__device__ unsigned g_arrive;               // grid-barrier counter

// ---------------------------------------------------------------------------
__global__ void zero_out_kernel(float4* __restrict__ o) {
    const int n4 = (T_LEN * BATCH * HDIM) / 4;
    for (int i = blockIdx.x * blockDim.x + threadIdx.x; i < n4;
         i += gridDim.x * blockDim.x)
        o[i] = make_float4(0.f, 0.f, 0.f, 0.f);
}

__global__ void zero_state_kernel() {
    int i = blockIdx.x * blockDim.x + threadIdx.x;  // 65536 needed
    if (i < 2 * 2 * BATCH * HDIM)
        (&g_h[0][0][0])[i] = 0.f;
    if (i == 0) g_arrive = 0u;
}

// ---------------------------------------------------------------------------
// Input projection GEMM (unchanged from R4): M=38400, N=2048, K=512.
// Output b-minor: xp[(t*2048 + n)*32 + b].
// ---------------------------------------------------------------------------
__global__ __launch_bounds__(256, 2)
void xproj_gemm(const float* __restrict__ x, const int* __restrict__ lens,
                const float* __restrict__ w, const float* __restrict__ b1,
                const float* __restrict__ b2, int rev)
{
    __shared__ float as[2][8][132];
    __shared__ float bs[2][8][132];
    float* __restrict__ out = g_xp[rev];

    const int tid = threadIdx.x;
    const int m0 = blockIdx.x * 128;
    const int n0 = blockIdx.y * 128;

    const int lr = tid >> 1;
    const int lk = (tid & 1) * 4;

    const int m = m0 + lr;
    const float* arow;
    if (!rev) {
        arow = x + (size_t)m * IDIM;
    } else {
        int t = m >> 5, b = m & 31;
        int st = lens[b] - 1 - t;
        if (st < 0) st = 0;
        arow = x + ((size_t)st * BATCH + b) * IDIM;
    }
    const float* brow = w + (size_t)(n0 + lr) * IDIM;

    float4 areg = *(const float4*)(arow + lk);
    float4 breg = *(const float4*)(brow + lk);

    u64 acc2[8][4];
#pragma unroll
    for (int i = 0; i < 8; i++)
#pragma unroll
        for (int p = 0; p < 4; p++) acc2[i][p] = 0ULL;

    const int wid = tid >> 5, lane = tid & 31;
    const int wm = (wid >> 1) * 32, wn = (wid & 1) * 64;
    const int lm = (lane & 3) * 4,  ln = (lane >> 2) * 4;

    as[0][lk + 0][lr] = areg.x; as[0][lk + 1][lr] = areg.y;
    as[0][lk + 2][lr] = areg.z; as[0][lk + 3][lr] = areg.w;
    bs[0][lk + 0][lr] = breg.x; bs[0][lk + 1][lr] = breg.y;
    bs[0][lk + 2][lr] = breg.z; bs[0][lk + 3][lr] = breg.w;
    __syncthreads();

    int buf = 0;
    for (int k0 = 8; k0 <= IDIM; k0 += 8) {
        const bool more = (k0 < IDIM);
        if (more) {
            areg = *(const float4*)(arow + k0 + lk);
            breg = *(const float4*)(brow + k0 + lk);
        }
#pragma unroll
        for (int kk = 0; kk < 8; kk++) {
            float4 a0  = *(const float4*)&as[buf][kk][wm + lm];
            float4 a1  = *(const float4*)&as[buf][kk][wm + lm + 16];
            ulonglong2 bq0 = *(const ulonglong2*)&bs[buf][kk][wn + ln];
            ulonglong2 bq1 = *(const ulonglong2*)&bs[buf][kk][wn + ln + 32];
            u64 b2v[4] = {bq0.x, bq0.y, bq1.x, bq1.y};
            float av[8] = {a0.x, a0.y, a0.z, a0.w, a1.x, a1.y, a1.z, a1.w};
#pragma unroll
            for (int i = 0; i < 8; i++) {
                u64 a2 = dup2(av[i]);
#pragma unroll
                for (int p = 0; p < 4; p++)
                    fma2(acc2[i][p], a2, b2v[p]);
            }
        }
        if (more) {
            buf ^= 1;
            as[buf][lk + 0][lr] = areg.x; as[buf][lk + 1][lr] = areg.y;
            as[buf][lk + 2][lr] = areg.z; as[buf][lk + 3][lr] = areg.w;
            bs[buf][lk + 0][lr] = breg.x; bs[buf][lk + 1][lr] = breg.y;
            bs[buf][lk + 2][lr] = breg.z; bs[buf][lk + 3][lr] = breg.w;
            __syncthreads();
        }
    }

    const int c0 = n0 + wn + ln;
    float bias[8];
#pragma unroll
    for (int p = 0; p < 4; p++) {
        int cc = c0 + (p & 1) * 2 + (p >> 1) * 32;
        bias[p * 2 + 0] = b1[cc + 0] + b2[cc + 0];
        bias[p * 2 + 1] = b1[cc + 1] + b2[cc + 1];
    }
#pragma unroll
    for (int i = 0; i < 8; i++) {
        int r = m0 + wm + lm + (i & 3) + ((i >= 4) ? 16 : 0);
        int t_ = r >> 5, b_ = r & 31;
        size_t base = ((size_t)t_ * G4) * 32 + b_;
#pragma unroll
        for (int p = 0; p < 4; p++) {
            int cc = c0 + (p & 1) * 2 + (p >> 1) * 32;
            float2 v = unp2(acc2[i][p]);
            out[base + (size_t)(cc + 0) * 32] = v.x + bias[p * 2 + 0];
            out[base + (size_t)(cc + 1) * 32] = v.y + bias[p * 2 + 1];
        }
    }
}

// ---------------------------------------------------------------------------
// Persistent recurrence: 128 CTAs = 2 dir x 64 j-blocks (8 j each), 256 thr.
// Full K per CTA; intra-CTA K split across 8 warps (64 k each); one grid
// barrier per step; global h double-buffered; cells register-resident.
// SMEM: ws 64KB (swizzled W) + hs 64KB (swizzled h) + red 32KB = 160KB.
// ---------------------------------------------------------------------------
#define SMEM_FLOATS (16384 + 16384 + 8192)
#define SMEM_BYTES  (SMEM_FLOATS * 4)

// word index of float4 chunk c (0..127) in row r, XOR-swizzled
#define WSW(r, c) (((r) << 9) + ((((c) ^ (((r) >> 2) & 7)) << 2)))
#define HSW(b, c) (((b) << 9) + ((((c) ^ (((b) >> 3) & 3)) << 2)))

__global__ __launch_bounds__(NTHR)
void lstm_persist(const float* __restrict__ whh_f,
                  const float* __restrict__ whh_b,
                  const int* __restrict__ lens, float* __restrict__ out)
{
    extern __shared__ float sm[];
    float* ws  = sm;                  // [32 gate-rows][512] swizzled
    float* hs  = sm + 16384;          // [32 b][512] swizzled
    float* red = sm + 32768;          // [8 ks][32 r][32 b]

    const int bid = blockIdx.x;
    const int dir = bid >> 6;
    const int j0  = (bid & 63) << 3;
    const int tid = threadIdx.x;
    const int ks  = tid >> 5;         // warp = k-slice (64 k)
    const int ln  = tid & 31;

    const float* __restrict__ whh = dir ? whh_b : whh_f;

    // ---- load W_hh slice once (swizzled) ----
    // ws row r = g*8 + jl  <->  W row g*512 + j0 + jl
#pragma unroll
    for (int it = 0; it < 16; it++) {
        int cid = it * 256 + tid;          // 0..4095 float4 chunks
        int r = cid >> 7, c = cid & 127;
        int g = r >> 3, jl = r & 7;
        float4 v = *(const float4*)(whh +
            (size_t)(g * HDIM + j0 + jl) * HDIM + (c << 2));
        *(float4*)&ws[WSW(r, c)] = v;
    }

    // compute identity: lane = rg*4 + bg  (rows rg*4..+3, b bg*8..+7)
    const int rg = ln >> 2;           // 0..7
    const int bg = ln & 3;            // 0..3

    // cell identity: one cell per thread
    const int b_c = tid & 31;
    const int j_c = tid >> 5;         // 0..7
    const int len_c = lens[b_c];

    float c_reg = 0.f, h_reg = 0.f;

    // h copy identity
    const int l16 = ln >> 4;          // 0..1
    const int l15 = ln & 15;          // 0..15

    __syncthreads();  // ws ready

    for (int t = 0; t < T_LEN; t++) {
        // Prefetch xp for this thread's cell (b-minor -> coalesced)
        const float* xb = g_xp[dir] + ((size_t)t * G4 + j0 + j_c) * 32 + b_c;
        float xg0 = __ldg(xb + (size_t)0 * 512 * 32);
        float xg1 = __ldg(xb + (size_t)1 * 512 * 32);
        float xg2 = __ldg(xb + (size_t)2 * 512 * 32);
        float xg3 = __ldg(xb + (size_t)3 * 512 * 32);

        // ---- per-warp h slice copy: [32 b][ks*64 .. +63] ----
        const float* __restrict__ hin = g_h[t & 1][dir];
#pragma unroll
        for (int i = 0; i < 16; i++) {
            int b = i * 2 + l16;
            int c = (ks << 4) + l15;
            float4 v = __ldcg((const float4*)(hin + (b << 9) + (c << 2)));
            *(float4*)&hs[HSW(b, c)] = v;
        }
        __syncwarp();

        // ---- compute: acc[rr 0..3][i 0..7] over 16 chunks of this slice ----
        float acc[4][8];
#pragma unroll
        for (int rr = 0; rr < 4; rr++)
#pragma unroll
            for (int i = 0; i < 8; i++) acc[rr][i] = 0.f;

        const int c0 = ks << 4;
#pragma unroll 2
        for (int c = c0; c < c0 + 16; c++) {
            float4 hv[8];
            const int hsw = ((c ^ bg) << 2);
#pragma unroll
            for (int i = 0; i < 8; i++)
                hv[i] = *(const float4*)&hs[(((bg << 3) + i) << 9) + hsw];
            float4 wv[4];
            const int wsw = ((c ^ rg) << 2);
#pragma unroll
            for (int rr = 0; rr < 4; rr++)
                wv[rr] = *(const float4*)&ws[(((rg << 2) + rr) << 9) + wsw];
#pragma unroll
            for (int rr = 0; rr < 4; rr++)
#pragma unroll
                for (int i = 0; i < 8; i++)
                    acc[rr][i] += wv[rr].x * hv[i].x + wv[rr].y * hv[i].y +
                                  wv[rr].z * hv[i].z + wv[rr].w * hv[i].w;
        }

        // ---- store partials to red[ks][r][b] ----
#pragma unroll
        for (int rr = 0; rr < 4; rr++) {
            int r = (rg << 2) + rr;
            float* dst = red + (ks << 10) + (r << 5) + (bg << 3);
            *(float4*)(dst + 0) = make_float4(acc[rr][0], acc[rr][1],
                                              acc[rr][2], acc[rr][3]);
            *(float4*)(dst + 4) = make_float4(acc[rr][4], acc[rr][5],
                                              acc[rr][6], acc[rr][7]);
        }
        __syncthreads();

        // ---- reduce 8 k-slices + LSTM cell (1 cell per thread) ----
        float s0 = xg0, s1 = xg1, s2 = xg2, s3 = xg3;
#pragma unroll
        for (int q = 0; q < 8; q++) {
            const float* pq = red + (q << 10) + b_c;
            s0 += pq[(0 * 8 + j_c) << 5];
            s1 += pq[(1 * 8 + j_c) << 5];
            s2 += pq[(2 * 8 + j_c) << 5];
            s3 += pq[(3 * 8 + j_c) << 5];
        }

        if (t < len_c) {
            float gi = 1.f / (1.f + __expf(-s0));
            float gf = 1.f / (1.f + __expf(-s1));
            float gg = tanhf(s2);
            float go = 1.f / (1.f + __expf(-s3));
            c_reg = gf * c_reg + gi * gg;
            h_reg = go * tanhf(c_reg);
            const int to = dir ? (len_c - 1 - t) : t;
            atomicAdd(out + ((size_t)to * BATCH + b_c) * HDIM + j0 + j_c, h_reg);
        }
        // always publish h (frozen value past length) to the other parity
        __stcg(g_h[(t + 1) & 1][dir] + (b_c << 9) + j0 + j_c, h_reg);

        // ---- single grid barrier ----
        __threadfence();
        __syncthreads();
        if (tid == 0) {
            atomicAdd(&g_arrive, 1u);
            const unsigned tgt = (unsigned)(t + 1) * NCTA;
            while (*(volatile unsigned*)&g_arrive < tgt) { }
            __threadfence();
        }
        __syncthreads();
    }

    // Final states: h_n (2,B,H) then c_n (2,B,H)
    const size_t base = (size_t)T_LEN * BATCH * HDIM;
    out[base + dir * BATCH * HDIM + (b_c << 9) + j0 + j_c] = h_reg;
    out[base + 2 * BATCH * HDIM + dir * BATCH * HDIM + (b_c << 9) + j0 + j_c] = c_reg;
}

// ---------------------------------------------------------------------------
extern "C" void kernel_launch(void* const* d_in, const int* in_sizes, int n_in,
                              void* d_out, int out_size) {
    (void)in_sizes; (void)n_in; (void)out_size;
    const float* x      = (const float*)d_in[0];
    const int*   lens   = (const int*)d_in[1];
    const float* w_ih_f = (const float*)d_in[2];
    const float* w_hh_f = (const float*)d_in[3];
    const float* b_ih_f = (const float*)d_in[4];
    const float* b_hh_f = (const float*)d_in[5];
    const float* w_ih_b = (const float*)d_in[6];
    const float* w_hh_b = (const float*)d_in[7];
    const float* b_ih_b = (const float*)d_in[8];
    const float* b_hh_b = (const float*)d_in[9];
    float* out = (float*)d_out;

    cudaFuncSetAttribute(lstm_persist,
                         cudaFuncAttributeMaxDynamicSharedMemorySize, SMEM_BYTES);

    zero_out_kernel<<<2048, 256>>>((float4*)out);
    zero_state_kernel<<<256, 256>>>();

    dim3 gg(300, 16);  // M/128 x N/128
    xproj_gemm<<<gg, 256>>>(x, lens, w_ih_f, b_ih_f, b_hh_f, 0);
    xproj_gemm<<<gg, 256>>>(x, lens, w_ih_b, b_ih_b, b_hh_b, 1);

    lstm_persist<<<NCTA, NTHR, SMEM_BYTES>>>(w_hh_f, w_hh_b, lens, out);
}